// round 2
// baseline (speedup 1.0000x reference)
#include <cuda_runtime.h>
#include <math.h>

#define HW   3136
#define NB   16
#define CC   256
#define C1   128
#define C4   64

// ---------------- scratch (no allocs allowed) ----------------
__device__ __align__(16) float g_cat[NB*CC*HW];   // [xh|xw|x1] concat, also holds x1 (ch 128..255)
__device__ __align__(16) float g_x2 [NB*C1*HW];   // x2 = gelu(bn(mlp))[ :,128:]
__device__ __align__(16) float g_x1 [NB*C1*HW];   // after fuse_h + bn + gelu + pos_w
__device__ __align__(16) float g_x1b[NB*C1*HW];   // after fuse_w
__device__ __align__(16) float g_x2h[NB*C1*HW];
__device__ __align__(16) float g_x2w[NB*C1*HW];
__device__ __align__(16) float g_x2f[NB*C1*HW];   // reweighted x2
__device__ float g_att[NB*C1];
__device__ float g_aw [NB*C1*3];

__device__ __forceinline__ float gelu_f(float x){
    return 0.5f*x*(1.0f+erff(x*0.70710678118654752f));
}

// ---------------- generic SGEMM: C[n][m][col] = sum_k A[m][k] * B[n][k][col] ----
// B rows come from B0 for k<ksplit, else B1 (virtual channel concat).
// MODE 0: +bias, BN, GELU; m<128 -> g_cat ch(128+m) with +pos_h ; m>=128 -> O1 ch(m-128)
// MODE 1: BN, GELU, +pos_w -> O0 (M=128)
// MODE 2: plain -> O0
template<int MODE>
__global__ __launch_bounds__(256)
void gemm_k(const float* __restrict__ A,
            const float* __restrict__ B0, int sB0,
            const float* __restrict__ B1, int sB1, int ksplit,
            int M, int K,
            float* __restrict__ O0, float* __restrict__ O1,
            const float* __restrict__ bias,
            const float* __restrict__ bng, const float* __restrict__ bnb,
            const float* __restrict__ bnm, const float* __restrict__ bnv,
            const float* __restrict__ postab)
{
    __shared__ float As[8][128];
    __shared__ float Bs[8][128];
    const int tid = threadIdx.x;
    const int tx = tid & 15, ty = tid >> 4;
    const int bn_ = blockIdx.x, bm = blockIdx.y, n = blockIdx.z;
    const int colBase = bn_*128;

    float acc[8][8];
#pragma unroll
    for (int i=0;i<8;i++)
#pragma unroll
        for (int j=0;j<8;j++) acc[i][j]=0.f;

    const int arow = tid >> 1;
    const int ak   = (tid & 1) << 2;
    const float* Aptr = A + (size_t)(bm*128 + arow)*K + ak;
    const int krow = tid >> 5;          // 0..7
    const int c4   = (tid & 31) << 2;   // 0..124
    const int col  = colBase + c4;

    for (int k0=0; k0<K; k0+=8){
        float4 av = *(const float4*)(Aptr + k0);
        As[ak+0][arow]=av.x; As[ak+1][arow]=av.y; As[ak+2][arow]=av.z; As[ak+3][arow]=av.w;

        float4 bv = make_float4(0.f,0.f,0.f,0.f);
        if (col < HW){
            int kg = k0 + krow;
            const float* bp = (kg < ksplit)
                ? (B0 + (size_t)n*sB0 + (size_t)kg*HW)
                : (B1 + (size_t)n*sB1 + (size_t)(kg-ksplit)*HW);
            bv = *(const float4*)(bp + col);
        }
        *(float4*)&Bs[krow][c4] = bv;
        __syncthreads();
#pragma unroll
        for (int kk=0;kk<8;kk++){
            float a0[8], b0[8];
            *(float4*)&a0[0] = *(const float4*)&As[kk][ty*8];
            *(float4*)&a0[4] = *(const float4*)&As[kk][ty*8+4];
            *(float4*)&b0[0] = *(const float4*)&Bs[kk][tx*8];
            *(float4*)&b0[4] = *(const float4*)&Bs[kk][tx*8+4];
#pragma unroll
            for (int i=0;i<8;i++)
#pragma unroll
                for (int j=0;j<8;j++) acc[i][j] += a0[i]*b0[j];
        }
        __syncthreads();
    }

#pragma unroll
    for (int i=0;i<8;i++){
        const int m = bm*128 + ty*8 + i;
        float sc=1.f, sh=0.f;
        if (MODE==0 || MODE==1){
            float sv = bng[m]*rsqrtf(bnv[m]+1e-5f);
            sc = sv; sh = bnb[m]-bnm[m]*sv;
        }
#pragma unroll
        for (int j=0;j<8;j++){
            const int cl = colBase + tx*8 + j;
            if (cl >= HW) continue;
            float v = acc[i][j];
            if (MODE==0){
                v += bias[m];
                v = gelu_f(v*sc + sh);
                int h = cl/56, w = cl - h*56;
                if (m < C1)
                    O0[(size_t)n*CC*HW + (size_t)(C1+m)*HW + cl] = v + postab[(w-h+56)*C1 + m];
                else
                    O1[(size_t)n*C1*HW + (size_t)(m-C1)*HW + cl] = v;
            } else if (MODE==1){
                v = gelu_f(v*sc + sh);
                int h = cl/56, w = cl - h*56;
                O0[(size_t)n*C1*HW + (size_t)m*HW + cl] = v + postab[(w-h+56)*C1 + m];
            } else {
                O0[(size_t)n*M*HW + (size_t)m*HW + cl] = v;
            }
        }
    }
}

// ---------------- strip conv along H (mixes full H with width-3 window) -------
// out[n,g,ho,w] = b[g*56+ho] + sum_{hi,kw} x1[n,g,hi,w+kw-1] * W[(g*56+ho)*56*3 + hi*3 + kw]
// x1 channel g lives at g_cat channel 128+g ; output written to g_cat channel g.
__global__ __launch_bounds__(224)
void strip_h_k(const float* __restrict__ W, const float* __restrict__ bias)
{
    const int g = blockIdx.x, n = blockIdx.y;
    __shared__ float in_s[56][58];
    const float* in = g_cat + (size_t)n*CC*HW + (size_t)(C1+g)*HW;
    const int tid = threadIdx.y*56 + threadIdx.x;
    for (int idx=tid; idx<56*58; idx+=224){
        int hi = idx/58, wp = idx%58;
        in_s[hi][wp] = (wp==0||wp==57) ? 0.f : in[hi*56 + wp-1];
    }
    __syncthreads();
    const int w = threadIdx.x;
    float* outp = g_cat + (size_t)n*CC*HW + (size_t)g*HW;
    for (int ho=threadIdx.y; ho<56; ho+=4){
        float acc = __ldg(&bias[g*56+ho]);
        const float* wr = W + (size_t)(g*56+ho)*56*3;
#pragma unroll 4
        for (int hi=0; hi<56; hi++){
            float w0=__ldg(&wr[hi*3]), w1=__ldg(&wr[hi*3+1]), w2=__ldg(&wr[hi*3+2]);
            acc += in_s[hi][w]*w0 + in_s[hi][w+1]*w1 + in_s[hi][w+2]*w2;
        }
        outp[ho*56 + w] = acc;
    }
}

// ---------------- strip conv along W (mixes full W with height-3 window) ------
// out[n,g,h,wo] = b[g*56+wo] + sum_{wi,kh} x1[n,64+g,h+kh-1,wi] * W[(g*56+wo)*56*3 + wi*3 + kh]
// input channel 64+g = g_cat ch 192+g ; output -> g_cat channel 64+g.
__global__ __launch_bounds__(224)
void strip_w_k(const float* __restrict__ W, const float* __restrict__ bias)
{
    const int g = blockIdx.x, n = blockIdx.y;
    __shared__ float in_s[58][57];
    __shared__ float out_s[56][57];
    const float* in = g_cat + (size_t)n*CC*HW + (size_t)(192+g)*HW;
    const int tid = threadIdx.y*56 + threadIdx.x;
    for (int idx=tid; idx<58*56; idx+=224){
        int hp = idx/56, wi = idx%56;
        in_s[hp][wi] = (hp==0||hp==57) ? 0.f : in[(hp-1)*56 + wi];
    }
    __syncthreads();
    const int h = threadIdx.x;   // lanes over h -> W loads uniform, smem stride 57 conflict-free
    for (int wo=threadIdx.y; wo<56; wo+=4){
        float acc = __ldg(&bias[g*56+wo]);
        const float* wr = W + (size_t)(g*56+wo)*56*3;
#pragma unroll 4
        for (int wi=0; wi<56; wi++){
            float w0=__ldg(&wr[wi*3]), w1=__ldg(&wr[wi*3+1]), w2=__ldg(&wr[wi*3+2]);
            acc += in_s[h][wi]*w0 + in_s[h+1][wi]*w1 + in_s[h+2][wi]*w2;
        }
        out_s[h][wo] = acc;
    }
    __syncthreads();
    float* outp = g_cat + (size_t)n*CC*HW + (size_t)(64+g)*HW;
    for (int idx=tid; idx<HW; idx+=224) outp[idx] = out_s[idx/56][idx%56];
}

// ---------------- fused depthwise 3x7 + 7x3 + spatial mean ---------------------
__global__ __launch_bounds__(256)
void dw_att_k(const float* __restrict__ Wh, const float* __restrict__ Ww)
{
    const int c = blockIdx.x, n = blockIdx.y;
    __shared__ float su[62][62];
    __shared__ float wk[42];
    __shared__ float red[256];
    const int tid = threadIdx.x;
    const float* in = g_x2 + (size_t)n*C1*HW + (size_t)c*HW;
    for (int idx=tid; idx<62*62; idx+=256){
        int r = idx/62, q = idx%62;
        int ih = r-3, iw = q-3;
        su[r][q] = (ih>=0 && ih<56 && iw>=0 && iw<56) ? in[ih*56+iw] : 0.f;
    }
    if (tid < 21)      wk[tid]    = Wh[c*21+tid];
    else if (tid < 42) wk[tid]    = Ww[c*21+tid-21];
    __syncthreads();
    float lsum = 0.f;
    float* oh_ = g_x2h + (size_t)n*C1*HW + (size_t)c*HW;
    float* ow_ = g_x2w + (size_t)n*C1*HW + (size_t)c*HW;
    for (int idx=tid; idx<HW; idx+=256){
        int oh = idx/56, ow = idx%56;
        float vh=0.f, vw=0.f;
#pragma unroll
        for (int kh=0;kh<3;kh++)
#pragma unroll
            for (int kw=0;kw<7;kw++)
                vh += su[oh+2+kh][ow+kw] * wk[kh*7+kw];
#pragma unroll
        for (int kh=0;kh<7;kh++)
#pragma unroll
            for (int kw=0;kw<3;kw++)
                vw += su[oh+kh][ow+2+kw] * wk[21+kh*3+kw];
        oh_[idx]=vh; ow_[idx]=vw;
        lsum += vh + vw + su[oh+3][ow+3];
    }
    red[tid]=lsum; __syncthreads();
    for (int s=128; s>0; s>>=1){ if (tid<s) red[tid]+=red[tid+s]; __syncthreads(); }
    if (tid==0) g_att[n*C1+c] = red[0] * (1.f/3136.f);
}

// ---------------- reweight MLP + softmax(3) ------------------------------------
__global__ __launch_bounds__(128)
void attw_k(const float* __restrict__ w1, const float* __restrict__ b1,
            const float* __restrict__ w2, const float* __restrict__ b2)
{
    const int n = blockIdx.x;
    __shared__ float at[128];
    __shared__ float hid[64];
    const int t = threadIdx.x;
    at[t] = g_att[n*128+t];
    __syncthreads();
    if (t < 64){
        float s = b1[t];
        for (int c=0;c<128;c++) s += at[c]*w1[t*128+c];
        hid[t] = gelu_f(s);
    }
    __syncthreads();
    float l[3];
#pragma unroll
    for (int k=0;k<3;k++){
        float s = b2[t*3+k];
        for (int j=0;j<64;j++) s += hid[j]*w2[(t*3+k)*64+j];
        l[k]=s;
    }
    float mx = fmaxf(l[0],fmaxf(l[1],l[2]));
    float e0=expf(l[0]-mx), e1=expf(l[1]-mx), e2=expf(l[2]-mx);
    float inv = 1.f/(e0+e1+e2);
    g_aw[n*384 + t*3 + 0] = e0*inv;
    g_aw[n*384 + t*3 + 1] = e1*inv;
    g_aw[n*384 + t*3 + 2] = e2*inv;
}

// ---------------- weighted combine of x2h / x2w / x2 ---------------------------
__global__ __launch_bounds__(256)
void comb_k()
{
    int i4 = blockIdx.x*256 + threadIdx.x;           // exactly NB*C1*HW/4 threads
    int i  = i4*4;
    int n = i/(C1*HW);
    int c = (i/HW)%C1;
    float a0=g_aw[n*384+c*3], a1=g_aw[n*384+c*3+1], a2=g_aw[n*384+c*3+2];
    float4 h = *(const float4*)&g_x2h[i];
    float4 w = *(const float4*)&g_x2w[i];
    float4 x = *(const float4*)&g_x2 [i];
    float4 o;
    o.x = h.x*a0 + w.x*a1 + x.x*a2;
    o.y = h.y*a0 + w.y*a1 + x.y*a2;
    o.z = h.z*a0 + w.z*a1 + x.z*a2;
    o.w = h.w*a0 + w.w*a1 + x.w*a2;
    *(float4*)&g_x2f[i] = o;
}

// ---------------- launch ---------------------------------------------------------
extern "C" void kernel_launch(void* const* d_in, const int* in_sizes, int n_in,
                              void* d_out, int out_size)
{
    const float* x           = (const float*)d_in[0];
    const float* mlp_w       = (const float*)d_in[1];
    const float* mlp_b       = (const float*)d_in[2];
    const float* mlp_bn_g    = (const float*)d_in[3];
    const float* mlp_bn_b    = (const float*)d_in[4];
    const float* mlp_bn_m    = (const float*)d_in[5];
    const float* mlp_bn_v    = (const float*)d_in[6];
    const float* pos_h_table = (const float*)d_in[7];
    const float* pos_w_table = (const float*)d_in[8];
    const float* proj_h_w    = (const float*)d_in[9];
    const float* proj_h_b    = (const float*)d_in[10];
    const float* proj_w_w    = (const float*)d_in[11];
    const float* proj_w_b    = (const float*)d_in[12];
    const float* fuse_h_w    = (const float*)d_in[13];
    const float* bn_g        = (const float*)d_in[14];
    const float* bn_b        = (const float*)d_in[15];
    const float* bn_m        = (const float*)d_in[16];
    const float* bn_v        = (const float*)d_in[17];
    const float* fuse_w_w    = (const float*)d_in[18];
    const float* fc_h_w      = (const float*)d_in[19];
    const float* fc_w_w      = (const float*)d_in[20];
    const float* rw_w1       = (const float*)d_in[21];
    const float* rw_b1       = (const float*)d_in[22];
    const float* rw_w2       = (const float*)d_in[23];
    const float* rw_b2       = (const float*)d_in[24];
    const float* fuse_out_w  = (const float*)d_in[25];

    float *pcat,*px2,*px1,*px1b,*px2h,*px2w,*px2f;
    cudaGetSymbolAddress((void**)&pcat,  g_cat);
    cudaGetSymbolAddress((void**)&px2,   g_x2);
    cudaGetSymbolAddress((void**)&px1,   g_x1);
    cudaGetSymbolAddress((void**)&px1b,  g_x1b);
    cudaGetSymbolAddress((void**)&px2h,  g_x2h);
    cudaGetSymbolAddress((void**)&px2w,  g_x2w);
    cudaGetSymbolAddress((void**)&px2f,  g_x2f);

    // 1) mlp pointwise + bias + BN + GELU ; split into x1(+pos_h)->g_cat[128..255] and x2->g_x2
    gemm_k<0><<<dim3(25,2,16),256>>>(mlp_w, x, CC*HW, x, CC*HW, CC, CC, CC,
                                     pcat, px2, mlp_b,
                                     mlp_bn_g, mlp_bn_b, mlp_bn_m, mlp_bn_v, pos_h_table);

    // 2) x2 branch (independent): depthwise + mean, reweight MLP, combine
    dw_att_k<<<dim3(C1,NB),256>>>(fc_h_w, fc_w_w);
    attw_k<<<NB,128>>>(rw_w1, rw_b1, rw_w2, rw_b2);
    comb_k<<<(NB*C1*HW/4 + 255)/256,256>>>();

    // 3) strip convs into g_cat channels [0..63] and [64..127]
    strip_h_k<<<dim3(C4,NB),dim3(56,4)>>>(proj_h_w, proj_h_b);
    strip_w_k<<<dim3(C4,NB),dim3(56,4)>>>(proj_w_w, proj_w_b);

    // 4) fuse_h GEMM over concat [xh|xw|x1] + BN + GELU + pos_w -> g_x1
    gemm_k<1><<<dim3(25,1,16),256>>>(fuse_h_w, pcat, CC*HW, pcat, CC*HW, CC, C1, CC,
                                     px1, nullptr, nullptr,
                                     bn_g, bn_b, bn_m, bn_v, pos_w_table);

    // 5) fuse_w GEMM over virtual concat [x1|x2] -> g_x1b
    gemm_k<2><<<dim3(25,1,16),256>>>(fuse_w_w, px1, C1*HW, px2, C1*HW, C1, C1, CC,
                                     px1b, nullptr, nullptr,
                                     nullptr, nullptr, nullptr, nullptr, nullptr);

    // 6) fuse_out GEMM over virtual concat [x1b|x2f] -> d_out
    gemm_k<2><<<dim3(25,2,16),256>>>(fuse_out_w, px1b, C1*HW, px2f, C1*HW, C1, CC, CC,
                                     (float*)d_out, nullptr, nullptr,
                                     nullptr, nullptr, nullptr, nullptr, nullptr);
}

// round 4
// speedup vs baseline: 1.7020x; 1.7020x over previous
#include <cuda_runtime.h>
#include <math.h>
#include <stdint.h>

#define HW   3136
#define NB   16
#define CC   256
#define C1   128
#define C4   64

// ---------------- scratch (no allocs allowed) ----------------
__device__ __align__(16) float g_cat[NB*CC*HW];   // [xh|xw|x1] concat, also holds x1 (ch 128..255)
__device__ __align__(16) float g_x2 [NB*C1*HW];   // x2 = gelu(bn(mlp))[ :,128:]
__device__ __align__(16) float g_x1 [NB*C1*HW];   // after fuse_h + bn + gelu + pos_w
__device__ __align__(16) float g_x1b[NB*C1*HW];   // after fuse_w
__device__ __align__(16) float g_x2h[NB*C1*HW];
__device__ __align__(16) float g_x2w[NB*C1*HW];
__device__ __align__(16) float g_x2f[NB*C1*HW];   // reweighted x2
__device__ float g_att[NB*C1];
__device__ float g_aw [NB*C1*3];

__device__ __forceinline__ float gelu_f(float x){
    return 0.5f*x*(1.0f+erff(x*0.70710678118654752f));
}

__device__ __forceinline__ uint32_t f2tf32(float x){
    uint32_t r;
    asm("cvt.rna.tf32.f32 %0, %1;" : "=r"(r) : "f"(x));
    return r;
}

__device__ __forceinline__ void mma_tf32(float* d, const uint32_t* a, const uint32_t* b){
    asm volatile(
        "mma.sync.aligned.m16n8k8.row.col.f32.tf32.tf32.f32 "
        "{%0,%1,%2,%3}, {%4,%5,%6,%7}, {%8,%9}, {%0,%1,%2,%3};"
        : "+f"(d[0]), "+f"(d[1]), "+f"(d[2]), "+f"(d[3])
        : "r"(a[0]), "r"(a[1]), "r"(a[2]), "r"(a[3]), "r"(b[0]), "r"(b[1]));
}

// ---------------- TF32 tensor-core GEMM ------------------------------------------
// C[n][m][col] = sum_k A[m][k] * B[n][k][col]; B rows from B0 for k<ksplit, else B1.
// Block tile: 128(m) x 128(col), K loop step 16. 8 warps as 2(m) x 4(col),
// warp tile 64x32, mma m16n8k8 tf32 (fp32 accumulate).
// MODE 0: +bias, BN, GELU; m<128 -> O0 ch(128+m) with +pos_h ; m>=128 -> O1 ch(m-128)
// MODE 1: BN, GELU, +pos_w -> O0 (M=128)
// MODE 2: plain -> O0
template<int MODE>
__global__ __launch_bounds__(256)
void gemm_k(const float* __restrict__ A,
            const float* __restrict__ B0, int sB0,
            const float* __restrict__ B1, int sB1, int ksplit,
            int M, int K,
            float* __restrict__ O0, float* __restrict__ O1,
            const float* __restrict__ bias,
            const float* __restrict__ bng, const float* __restrict__ bnb,
            const float* __restrict__ bnm, const float* __restrict__ bnv,
            const float* __restrict__ postab)
{
    __shared__ uint32_t Asm[16][136];   // [k][m], +8 pad -> conflict-free frag loads
    __shared__ uint32_t Bsm[16][136];   // [k][n]

    const int tid = threadIdx.x;
    const int lane = tid & 31;
    const int warp = tid >> 5;
    const int wm = warp >> 2;            // 0..1
    const int wn = warp & 3;             // 0..3
    const int group = lane >> 2;         // 0..7
    const int tig   = lane & 3;          // 0..3

    const int bn_ = blockIdx.x, bm = blockIdx.y, n = blockIdx.z;
    const int colBase = bn_*128;

    float acc[4][4][4];
#pragma unroll
    for (int i=0;i<4;i++)
#pragma unroll
        for (int j=0;j<4;j++)
#pragma unroll
            for (int c=0;c<4;c++) acc[i][j][c]=0.f;

    // global A load mapping: 128 rows x 16 k per tile, 2 float4 per thread
    const int arow = tid >> 1;                 // 0..127
    const int af4  = (tid & 1) * 2;            // 0 or 2 (each covers 2 float4 = 8 k)
    const float* Aptr = A + (size_t)(bm*128 + arow)*K + af4*4;

    // global B load mapping: 16 k rows x 128 cols, 2 float4 per thread
    const int brow = tid >> 4;                 // 0..15
    const int bcol = (tid & 15) * 8;           // 0..120
    const int gcol = colBase + bcol;

    const int mw = wm*64;                      // warp m base within block
    const int nw = wn*32;                      // warp n base within block

    for (int k0=0; k0<K; k0+=16){
        // ---- fetch globals to regs ----
        float4 av0 = *(const float4*)(Aptr + k0);
        float4 av1 = *(const float4*)(Aptr + k0 + 4);
        float4 bv0 = make_float4(0.f,0.f,0.f,0.f);
        float4 bv1 = make_float4(0.f,0.f,0.f,0.f);
        {
            int kg = k0 + brow;
            const float* bp = (kg < ksplit)
                ? (B0 + (size_t)n*sB0 + (size_t)kg*HW)
                : (B1 + (size_t)n*sB1 + (size_t)(kg-ksplit)*HW);
            if (gcol < HW){
                bv0 = *(const float4*)(bp + gcol);
                if (gcol + 4 < HW) bv1 = *(const float4*)(bp + gcol + 4);
            }
        }
        __syncthreads();
        // ---- store to smem (convert to tf32 bits) ----
        Asm[af4*4+0][arow] = f2tf32(av0.x);
        Asm[af4*4+1][arow] = f2tf32(av0.y);
        Asm[af4*4+2][arow] = f2tf32(av0.z);
        Asm[af4*4+3][arow] = f2tf32(av0.w);
        Asm[af4*4+4][arow] = f2tf32(av1.x);
        Asm[af4*4+5][arow] = f2tf32(av1.y);
        Asm[af4*4+6][arow] = f2tf32(av1.z);
        Asm[af4*4+7][arow] = f2tf32(av1.w);
        {
            uint4 u0, u1;
            u0.x=f2tf32(bv0.x); u0.y=f2tf32(bv0.y); u0.z=f2tf32(bv0.z); u0.w=f2tf32(bv0.w);
            u1.x=f2tf32(bv1.x); u1.y=f2tf32(bv1.y); u1.z=f2tf32(bv1.z); u1.w=f2tf32(bv1.w);
            *(uint4*)&Bsm[brow][bcol]   = u0;
            *(uint4*)&Bsm[brow][bcol+4] = u1;
        }
        __syncthreads();
        // ---- compute: 2 k8 sub-steps ----
#pragma unroll
        for (int ks=0; ks<16; ks+=8){
            uint32_t afr[4][4], bfr[4][2];
#pragma unroll
            for (int im=0; im<4; im++){
                int mr = mw + im*16 + group;
                afr[im][0] = Asm[ks+tig  ][mr];
                afr[im][1] = Asm[ks+tig  ][mr+8];
                afr[im][2] = Asm[ks+tig+4][mr];
                afr[im][3] = Asm[ks+tig+4][mr+8];
            }
#pragma unroll
            for (int in=0; in<4; in++){
                int nc = nw + in*8 + group;
                bfr[in][0] = Bsm[ks+tig  ][nc];
                bfr[in][1] = Bsm[ks+tig+4][nc];
            }
#pragma unroll
            for (int im=0; im<4; im++)
#pragma unroll
                for (int in=0; in<4; in++)
                    mma_tf32(acc[im][in], afr[im], bfr[in]);
        }
    }

    // ---- epilogue ----
#pragma unroll
    for (int im=0; im<4; im++){
#pragma unroll
        for (int half=0; half<2; half++){
            const int m = bm*128 + mw + im*16 + group + half*8;
            float sc=1.f, sh=0.f, bs=0.f;
            if (MODE==0 || MODE==1){
                float sv = bng[m]*rsqrtf(bnv[m]+1e-5f);
                sc = sv; sh = bnb[m]-bnm[m]*sv;
            }
            if (MODE==0) bs = bias[m];
#pragma unroll
            for (int in=0; in<4; in++){
#pragma unroll
                for (int jc=0; jc<2; jc++){
                    const int cl = colBase + nw + in*8 + tig*2 + jc;
                    if (cl >= HW) continue;
                    float v = acc[im][in][half*2 + jc];
                    if (MODE==0){
                        v = gelu_f((v + bs)*sc + sh);
                        int h = cl/56, w = cl - h*56;
                        if (m < C1)
                            O0[(size_t)n*CC*HW + (size_t)(C1+m)*HW + cl] = v + postab[(w-h+56)*C1 + m];
                        else
                            O1[(size_t)n*C1*HW + (size_t)(m-C1)*HW + cl] = v;
                    } else if (MODE==1){
                        v = gelu_f(v*sc + sh);
                        int h = cl/56, w = cl - h*56;
                        O0[(size_t)n*C1*HW + (size_t)m*HW + cl] = v + postab[(w-h+56)*C1 + m];
                    } else {
                        O0[(size_t)n*M*HW + (size_t)m*HW + cl] = v;
                    }
                }
            }
        }
    }
}

// ---------------- strip conv along H (mixes full H with width-3 window) -------
__global__ __launch_bounds__(224)
void strip_h_k(const float* __restrict__ W, const float* __restrict__ bias)
{
    const int g = blockIdx.x, n = blockIdx.y;
    __shared__ float in_s[56][58];
    const float* in = g_cat + (size_t)n*CC*HW + (size_t)(C1+g)*HW;
    const int tid = threadIdx.y*56 + threadIdx.x;
    for (int idx=tid; idx<56*58; idx+=224){
        int hi = idx/58, wp = idx%58;
        in_s[hi][wp] = (wp==0||wp==57) ? 0.f : in[hi*56 + wp-1];
    }
    __syncthreads();
    const int w = threadIdx.x;
    float* outp = g_cat + (size_t)n*CC*HW + (size_t)g*HW;
    for (int ho=threadIdx.y; ho<56; ho+=4){
        float acc = __ldg(&bias[g*56+ho]);
        const float* wr = W + (size_t)(g*56+ho)*56*3;
#pragma unroll 4
        for (int hi=0; hi<56; hi++){
            float w0=__ldg(&wr[hi*3]), w1=__ldg(&wr[hi*3+1]), w2=__ldg(&wr[hi*3+2]);
            acc += in_s[hi][w]*w0 + in_s[hi][w+1]*w1 + in_s[hi][w+2]*w2;
        }
        outp[ho*56 + w] = acc;
    }
}

// ---------------- strip conv along W -------------------------------------------
__global__ __launch_bounds__(224)
void strip_w_k(const float* __restrict__ W, const float* __restrict__ bias)
{
    const int g = blockIdx.x, n = blockIdx.y;
    __shared__ float in_s[58][57];
    __shared__ float out_s[56][57];
    const float* in = g_cat + (size_t)n*CC*HW + (size_t)(192+g)*HW;
    const int tid = threadIdx.y*56 + threadIdx.x;
    for (int idx=tid; idx<58*56; idx+=224){
        int hp = idx/56, wi = idx%56;
        in_s[hp][wi] = (hp==0||hp==57) ? 0.f : in[(hp-1)*56 + wi];
    }
    __syncthreads();
    const int h = threadIdx.x;
    for (int wo=threadIdx.y; wo<56; wo+=4){
        float acc = __ldg(&bias[g*56+wo]);
        const float* wr = W + (size_t)(g*56+wo)*56*3;
#pragma unroll 4
        for (int wi=0; wi<56; wi++){
            float w0=__ldg(&wr[wi*3]), w1=__ldg(&wr[wi*3+1]), w2=__ldg(&wr[wi*3+2]);
            acc += in_s[h][wi]*w0 + in_s[h+1][wi]*w1 + in_s[h+2][wi]*w2;
        }
        out_s[h][wo] = acc;
    }
    __syncthreads();
    float* outp = g_cat + (size_t)n*CC*HW + (size_t)(64+g)*HW;
    for (int idx=tid; idx<HW; idx+=224) outp[idx] = out_s[idx/56][idx%56];
}

// ---------------- fused depthwise 3x7 + 7x3 + spatial mean ---------------------
__global__ __launch_bounds__(256)
void dw_att_k(const float* __restrict__ Wh, const float* __restrict__ Ww)
{
    const int c = blockIdx.x, n = blockIdx.y;
    __shared__ float su[62][62];
    __shared__ float wk[42];
    __shared__ float red[256];
    const int tid = threadIdx.x;
    const float* in = g_x2 + (size_t)n*C1*HW + (size_t)c*HW;
    for (int idx=tid; idx<62*62; idx+=256){
        int r = idx/62, q = idx%62;
        int ih = r-3, iw = q-3;
        su[r][q] = (ih>=0 && ih<56 && iw>=0 && iw<56) ? in[ih*56+iw] : 0.f;
    }
    if (tid < 21)      wk[tid]    = Wh[c*21+tid];
    else if (tid < 42) wk[tid]    = Ww[c*21+tid-21];
    __syncthreads();
    float lsum = 0.f;
    float* oh_ = g_x2h + (size_t)n*C1*HW + (size_t)c*HW;
    float* ow_ = g_x2w + (size_t)n*C1*HW + (size_t)c*HW;
    for (int idx=tid; idx<HW; idx+=256){
        int oh = idx/56, ow = idx%56;
        float vh=0.f, vw=0.f;
#pragma unroll
        for (int kh=0;kh<3;kh++)
#pragma unroll
            for (int kw=0;kw<7;kw++)
                vh += su[oh+2+kh][ow+kw] * wk[kh*7+kw];
#pragma unroll
        for (int kh=0;kh<7;kh++)
#pragma unroll
            for (int kw=0;kw<3;kw++)
                vw += su[oh+kh][ow+2+kw] * wk[21+kh*3+kw];
        oh_[idx]=vh; ow_[idx]=vw;
        lsum += vh + vw + su[oh+3][ow+3];
    }
    red[tid]=lsum; __syncthreads();
    for (int s=128; s>0; s>>=1){ if (tid<s) red[tid]+=red[tid+s]; __syncthreads(); }
    if (tid==0) g_att[n*C1+c] = red[0] * (1.f/3136.f);
}

// ---------------- reweight MLP + softmax(3) ------------------------------------
__global__ __launch_bounds__(128)
void attw_k(const float* __restrict__ w1, const float* __restrict__ b1,
            const float* __restrict__ w2, const float* __restrict__ b2)
{
    const int n = blockIdx.x;
    __shared__ float at[128];
    __shared__ float hid[64];
    const int t = threadIdx.x;
    at[t] = g_att[n*128+t];
    __syncthreads();
    if (t < 64){
        float s = b1[t];
        for (int c=0;c<128;c++) s += at[c]*w1[t*128+c];
        hid[t] = gelu_f(s);
    }
    __syncthreads();
    float l[3];
#pragma unroll
    for (int k=0;k<3;k++){
        float s = b2[t*3+k];
        for (int j=0;j<64;j++) s += hid[j]*w2[(t*3+k)*64+j];
        l[k]=s;
    }
    float mx = fmaxf(l[0],fmaxf(l[1],l[2]));
    float e0=expf(l[0]-mx), e1=expf(l[1]-mx), e2=expf(l[2]-mx);
    float inv = 1.f/(e0+e1+e2);
    g_aw[n*384 + t*3 + 0] = e0*inv;
    g_aw[n*384 + t*3 + 1] = e1*inv;
    g_aw[n*384 + t*3 + 2] = e2*inv;
}

// ---------------- weighted combine of x2h / x2w / x2 ---------------------------
__global__ __launch_bounds__(256)
void comb_k()
{
    int i4 = blockIdx.x*256 + threadIdx.x;
    int i  = i4*4;
    int n = i/(C1*HW);
    int c = (i/HW)%C1;
    float a0=g_aw[n*384+c*3], a1=g_aw[n*384+c*3+1], a2=g_aw[n*384+c*3+2];
    float4 h = *(const float4*)&g_x2h[i];
    float4 w = *(const float4*)&g_x2w[i];
    float4 x = *(const float4*)&g_x2 [i];
    float4 o;
    o.x = h.x*a0 + w.x*a1 + x.x*a2;
    o.y = h.y*a0 + w.y*a1 + x.y*a2;
    o.z = h.z*a0 + w.z*a1 + x.z*a2;
    o.w = h.w*a0 + w.w*a1 + x.w*a2;
    *(float4*)&g_x2f[i] = o;
}

// ---------------- launch ---------------------------------------------------------
extern "C" void kernel_launch(void* const* d_in, const int* in_sizes, int n_in,
                              void* d_out, int out_size)
{
    const float* x           = (const float*)d_in[0];
    const float* mlp_w       = (const float*)d_in[1];
    const float* mlp_b       = (const float*)d_in[2];
    const float* mlp_bn_g    = (const float*)d_in[3];
    const float* mlp_bn_b    = (const float*)d_in[4];
    const float* mlp_bn_m    = (const float*)d_in[5];
    const float* mlp_bn_v    = (const float*)d_in[6];
    const float* pos_h_table = (const float*)d_in[7];
    const float* pos_w_table = (const float*)d_in[8];
    const float* proj_h_w    = (const float*)d_in[9];
    const float* proj_h_b    = (const float*)d_in[10];
    const float* proj_w_w    = (const float*)d_in[11];
    const float* proj_w_b    = (const float*)d_in[12];
    const float* fuse_h_w    = (const float*)d_in[13];
    const float* bn_g        = (const float*)d_in[14];
    const float* bn_b        = (const float*)d_in[15];
    const float* bn_m        = (const float*)d_in[16];
    const float* bn_v        = (const float*)d_in[17];
    const float* fuse_w_w    = (const float*)d_in[18];
    const float* fc_h_w      = (const float*)d_in[19];
    const float* fc_w_w      = (const float*)d_in[20];
    const float* rw_w1       = (const float*)d_in[21];
    const float* rw_b1       = (const float*)d_in[22];
    const float* rw_w2       = (const float*)d_in[23];
    const float* rw_b2       = (const float*)d_in[24];
    const float* fuse_out_w  = (const float*)d_in[25];

    float *pcat,*px2,*px1,*px1b,*px2h,*px2w,*px2f;
    cudaGetSymbolAddress((void**)&pcat,  g_cat);
    cudaGetSymbolAddress((void**)&px2,   g_x2);
    cudaGetSymbolAddress((void**)&px1,   g_x1);
    cudaGetSymbolAddress((void**)&px1b,  g_x1b);
    cudaGetSymbolAddress((void**)&px2h,  g_x2h);
    cudaGetSymbolAddress((void**)&px2w,  g_x2w);
    cudaGetSymbolAddress((void**)&px2f,  g_x2f);

    // 1) mlp pointwise + bias + BN + GELU ; split into x1(+pos_h)->g_cat[128..255] and x2->g_x2
    gemm_k<0><<<dim3(25,2,16),256>>>(mlp_w, x, CC*HW, x, CC*HW, CC, CC, CC,
                                     pcat, px2, mlp_b,
                                     mlp_bn_g, mlp_bn_b, mlp_bn_m, mlp_bn_v, pos_h_table);

    // 2) x2 branch (independent): depthwise + mean, reweight MLP, combine
    dw_att_k<<<dim3(C1,NB),256>>>(fc_h_w, fc_w_w);
    attw_k<<<NB,128>>>(rw_w1, rw_b1, rw_w2, rw_b2);
    comb_k<<<(NB*C1*HW/4 + 255)/256,256>>>();

    // 3) strip convs into g_cat channels [0..63] and [64..127]
    strip_h_k<<<dim3(C4,NB),dim3(56,4)>>>(proj_h_w, proj_h_b);
    strip_w_k<<<dim3(C4,NB),dim3(56,4)>>>(proj_w_w, proj_w_b);

    // 4) fuse_h GEMM over concat [xh|xw|x1] + BN + GELU + pos_w -> g_x1
    gemm_k<1><<<dim3(25,1,16),256>>>(fuse_h_w, pcat, CC*HW, pcat, CC*HW, CC, C1, CC,
                                     px1, nullptr, nullptr,
                                     bn_g, bn_b, bn_m, bn_v, pos_w_table);

    // 5) fuse_w GEMM over virtual concat [x1|x2] -> g_x1b
    gemm_k<2><<<dim3(25,1,16),256>>>(fuse_w_w, px1, C1*HW, px2, C1*HW, C1, C1, CC,
                                     px1b, nullptr, nullptr,
                                     nullptr, nullptr, nullptr, nullptr, nullptr);

    // 6) fuse_out GEMM over virtual concat [x1b|x2f] -> d_out
    gemm_k<2><<<dim3(25,2,16),256>>>(fuse_out_w, px1b, C1*HW, px2f, C1*HW, C1, CC, CC,
                                     (float*)d_out, nullptr, nullptr,
                                     nullptr, nullptr, nullptr, nullptr, nullptr);
}